// round 1
// baseline (speedup 1.0000x reference)
#include <cuda_runtime.h>

// Problem constants
#define B_  4
#define L_  4096
#define H_  1024
#define U_  1024
#define M_  (B_*L_)          // 16384 rows

constexpr int CL = 64;            // scan chunk length
constexpr int NC = L_ / CL;       // 64 chunks per sequence

// ---------------- scratch (device globals; no allocation allowed) -------------
__device__ float g_inT[(size_t)M_ * H_];   // tf32-rounded inputs (64 MB)
__device__ float g_WiT[(size_t)U_ * H_];   // tf32-rounded Wi      (4 MB)
__device__ float g_WoT[(size_t)H_ * U_];   // tf32-rounded Wo      (4 MB)
__device__ float g_u  [(size_t)M_ * U_];   // u / scanned x        (64 MB)
__device__ float g_v  [(size_t)B_ * NC * U_]; // chunk carries      (1 MB)

// ---------------- helpers ----------------------------------------------------
__device__ __forceinline__ float to_tf32(float x) {
    unsigned u;
    asm("cvt.rna.tf32.f32 %0, %1;" : "=r"(u) : "f"(x));
    return __uint_as_float(u);
}

__device__ __forceinline__ void cp_async16(float* smem_dst, const float* gsrc) {
    unsigned s = (unsigned)__cvta_generic_to_shared(smem_dst);
    asm volatile("cp.async.cg.shared.global [%0], [%1], 16;\n" :: "r"(s), "l"(gsrc));
}
__device__ __forceinline__ void cp_commit() {
    asm volatile("cp.async.commit_group;\n" ::: "memory");
}

__device__ __forceinline__ void mma_tf32(float* d, const float* a, const float* b) {
    const unsigned* A = reinterpret_cast<const unsigned*>(a);
    const unsigned* Bv = reinterpret_cast<const unsigned*>(b);
    asm volatile(
        "mma.sync.aligned.m16n8k8.row.col.f32.tf32.tf32.f32 "
        "{%0,%1,%2,%3}, {%4,%5,%6,%7}, {%8,%9}, {%0,%1,%2,%3};\n"
        : "+f"(d[0]), "+f"(d[1]), "+f"(d[2]), "+f"(d[3])
        : "r"(A[0]), "r"(A[1]), "r"(A[2]), "r"(A[3]),
          "r"(Bv[0]), "r"(Bv[1]));
}

// ---------------- tf32 pre-rounding pass -------------------------------------
__global__ void cvt_tf32_kernel(int sel, const float4* __restrict__ src) {
    float4* dst;
    int n4;
    if (sel == 0)      { dst = reinterpret_cast<float4*>(g_inT); n4 = (int)((size_t)M_ * H_ / 4); }
    else if (sel == 1) { dst = reinterpret_cast<float4*>(g_WiT); n4 = U_ * H_ / 4; }
    else               { dst = reinterpret_cast<float4*>(g_WoT); n4 = H_ * U_ / 4; }
    int i = blockIdx.x * blockDim.x + threadIdx.x;
    int stride = gridDim.x * blockDim.x;
    for (; i < n4; i += stride) {
        float4 v = src[i];
        v.x = to_tf32(v.x); v.y = to_tf32(v.y);
        v.z = to_tf32(v.z); v.w = to_tf32(v.w);
        dst[i] = v;
    }
}

// ---------------- TF32 tensor-core GEMM: C[M,N] = A[M,K] * B[N,K]^T + bias ---
// BM=128, BN=128, BK=32; 8 warps, warp tile 32x64, mma m16n8k8.
constexpr int BM = 128, BN = 128, BK = 32;
constexpr int LDK = 36;                 // padded smem row stride (bank-conflict-free)
constexpr int TILE = BM * LDK;          // floats per (operand, buffer)
constexpr int GEMM_SMEM_BYTES = 4 * TILE * (int)sizeof(float);  // 73728

__global__ __launch_bounds__(256, 2)
void gemm_tf32_kernel(int sel, const float* __restrict__ bias, float* __restrict__ Cext)
{
    const float* __restrict__ A  = (sel == 0) ? g_inT : g_u;
    const float* __restrict__ Bm = (sel == 0) ? g_WiT : g_WoT;
    float* __restrict__ C        = (sel == 0) ? g_u   : Cext;
    constexpr int K = H_;        // 1024
    constexpr int N = U_;        // 1024 (same for both GEMMs)

    extern __shared__ float smem_g[];
    float* sA = smem_g;              // [2][TILE]
    float* sB = smem_g + 2 * TILE;   // [2][TILE]

    const int tid  = threadIdx.x;
    const int bm   = blockIdx.y * BM;
    const int bn   = blockIdx.x * BN;
    const int warp = tid >> 5, lane = tid & 31;
    const int wm   = (warp >> 1) * 32;   // warp grid 4(M) x 2(N)
    const int wn   = (warp & 1) * 64;
    const int gid  = lane >> 2, t4 = lane & 3;

    const int lrow = tid >> 3;           // 0..31
    const int lcol = (tid & 7) * 4;      // 0..28 step 4

    const float* Ag = A  + (size_t)(bm + lrow) * K + lcol;
    const float* Bg = Bm + (size_t)(bn + lrow) * K + lcol;

    float acc[2][8][4];
    #pragma unroll
    for (int mt = 0; mt < 2; mt++)
        #pragma unroll
        for (int nt = 0; nt < 8; nt++)
            #pragma unroll
            for (int i = 0; i < 4; i++) acc[mt][nt][i] = 0.f;

    // stage tile 0 into buffer 0
    #pragma unroll
    for (int i = 0; i < 4; i++) {
        cp_async16(sA + (lrow + i * 32) * LDK + lcol, Ag + (size_t)i * 32 * K);
        cp_async16(sB + (lrow + i * 32) * LDK + lcol, Bg + (size_t)i * 32 * K);
    }
    cp_commit();

    constexpr int NKT = K / BK;   // 32
    #pragma unroll 1
    for (int kt = 0; kt < NKT; kt++) {
        asm volatile("cp.async.wait_group 0;\n" ::: "memory");
        __syncthreads();
        const int buf = kt & 1;

        if (kt + 1 < NKT) {
            const float* An = Ag + (kt + 1) * BK;
            const float* Bn = Bg + (kt + 1) * BK;
            float* dA = sA + (buf ^ 1) * TILE;
            float* dB = sB + (buf ^ 1) * TILE;
            #pragma unroll
            for (int i = 0; i < 4; i++) {
                cp_async16(dA + (lrow + i * 32) * LDK + lcol, An + (size_t)i * 32 * K);
                cp_async16(dB + (lrow + i * 32) * LDK + lcol, Bn + (size_t)i * 32 * K);
            }
            cp_commit();
        }

        const float* a_s = sA + buf * TILE;
        const float* b_s = sB + buf * TILE;

        #pragma unroll
        for (int ks = 0; ks < 4; ks++) {
            const int k0 = ks * 8;
            float afr[2][4], bfr[8][2];
            #pragma unroll
            for (int mt = 0; mt < 2; mt++) {
                const int m0 = wm + mt * 16;
                afr[mt][0] = a_s[(m0 + gid    ) * LDK + k0 + t4];
                afr[mt][1] = a_s[(m0 + gid + 8) * LDK + k0 + t4];
                afr[mt][2] = a_s[(m0 + gid    ) * LDK + k0 + t4 + 4];
                afr[mt][3] = a_s[(m0 + gid + 8) * LDK + k0 + t4 + 4];
            }
            #pragma unroll
            for (int nt = 0; nt < 8; nt++) {
                const int n0 = wn + nt * 8;
                bfr[nt][0] = b_s[(n0 + gid) * LDK + k0 + t4];
                bfr[nt][1] = b_s[(n0 + gid) * LDK + k0 + t4 + 4];
            }
            #pragma unroll
            for (int mt = 0; mt < 2; mt++)
                #pragma unroll
                for (int nt = 0; nt < 8; nt++)
                    mma_tf32(acc[mt][nt], afr[mt], bfr[nt]);
        }
    }

    // epilogue: add bias, write fp32
    #pragma unroll
    for (int mt = 0; mt < 2; mt++) {
        const int row = bm + wm + mt * 16 + gid;
        #pragma unroll
        for (int nt = 0; nt < 8; nt++) {
            const int col = bn + wn + nt * 8 + t4 * 2;
            const float b0 = bias[col], b1 = bias[col + 1];
            float2 v0 = make_float2(acc[mt][nt][0] + b0, acc[mt][nt][1] + b1);
            float2 v1 = make_float2(acc[mt][nt][2] + b0, acc[mt][nt][3] + b1);
            *reinterpret_cast<float2*>(&C[(size_t)row * N + col]) = v0;
            *reinterpret_cast<float2*>(&C[(size_t)(row + 8) * N + col]) = v1;
        }
    }
}

// ---------------- scan: h_t = lam*h_{t-1} + u_t, chunked ---------------------
// K1: local scan within each 64-chunk; record chunk-final value into g_v.
__global__ void scan_local_kernel(const float* __restrict__ plog)
{
    const int g  = blockIdx.x * 256 + threadIdx.x;   // B*NC*U threads
    const int uu = g & (U_ - 1);
    const int c  = (g >> 10) & (NC - 1);
    const int b  = g >> 16;
    const float lam = expf(-expf(plog[uu]));
    float* p = g_u + (size_t)(b * L_ + c * CL) * U_ + uu;
    float h = 0.f;
    #pragma unroll 8
    for (int t = 0; t < CL; t++) {
        float v = p[(size_t)t * U_];
        h = fmaf(lam, h, v);
        p[(size_t)t * U_] = h;
    }
    g_v[(size_t)(b * NC + c) * U_ + uu] = h;
}

// K2: exclusive scan of chunk carries along the chunk axis (per b,u).
__global__ void scan_carry_kernel(const float* __restrict__ plog)
{
    const int g  = blockIdx.x * 256 + threadIdx.x;   // B*U threads
    const int uu = g & (U_ - 1);
    const int b  = g >> 10;
    const float nu   = expf(plog[uu]);
    const float lamC = expf(-(float)CL * nu);
    float* p = g_v + (size_t)b * NC * U_ + uu;
    float carry = 0.f;
    #pragma unroll 1
    for (int c = 0; c < NC; c++) {
        float t = p[(size_t)c * U_];
        p[(size_t)c * U_] = carry;           // exclusive
        carry = fmaf(lamC, carry, t);
    }
}

// K3: apply carry, multiply gamma, round to tf32 for GEMM2 operand.
__global__ void scan_apply_kernel(const float* __restrict__ plog)
{
    const int g  = blockIdx.x * 256 + threadIdx.x;   // B*NC*U threads
    const int uu = g & (U_ - 1);
    const int c  = (g >> 10) & (NC - 1);
    const int b  = g >> 16;
    const float nu  = expf(plog[uu]);
    const float lam = expf(-nu);
    const float gam = expf(plog[U_ + uu]);
    const float carry = g_v[(size_t)(b * NC + c) * U_ + uu];
    float* p = g_u + (size_t)(b * L_ + c * CL) * U_ + uu;
    float pw = lam;
    #pragma unroll 8
    for (int t = 0; t < CL; t++) {
        float v = p[(size_t)t * U_] + pw * carry;   // h_t = local + lam^{t+1}*carry
        p[(size_t)t * U_] = to_tf32(v * gam);
        pw *= lam;
    }
}

// ---------------- launch ------------------------------------------------------
extern "C" void kernel_launch(void* const* d_in, const int* in_sizes, int n_in,
                              void* d_out, int out_size)
{
    const float* inputs = (const float*)d_in[0];
    const float* Wi     = (const float*)d_in[1];
    const float* bi     = (const float*)d_in[2];
    const float* Wo     = (const float*)d_in[3];
    const float* bo     = (const float*)d_in[4];
    const float* plog   = (const float*)d_in[5];
    float* out = (float*)d_out;

    cudaFuncSetAttribute(gemm_tf32_kernel,
                         cudaFuncAttributeMaxDynamicSharedMemorySize,
                         GEMM_SMEM_BYTES);

    // tf32 pre-rounding (needed to avoid MMA truncation bias)
    cvt_tf32_kernel<<<2048, 256>>>(0, (const float4*)inputs);
    cvt_tf32_kernel<<<256, 256>>>(1, (const float4*)Wi);
    cvt_tf32_kernel<<<256, 256>>>(2, (const float4*)Wo);

    // GEMM1: u = inputs * Wi^T + bi   -> g_u
    gemm_tf32_kernel<<<dim3(U_ / BN, M_ / BM), 256, GEMM_SMEM_BYTES>>>(0, bi, nullptr);

    // scan (chunked linear recurrence) + gamma, in place on g_u
    scan_local_kernel<<<(B_ * NC * U_) / 256, 256>>>(plog);
    scan_carry_kernel<<<(B_ * U_) / 256, 256>>>(plog);
    scan_apply_kernel<<<(B_ * NC * U_) / 256, 256>>>(plog);

    // GEMM2: out = x * Wo^T + bo
    gemm_tf32_kernel<<<dim3(H_ / BN, M_ / BM), 256, GEMM_SMEM_BYTES>>>(1, bo, out);
}